// round 3
// baseline (speedup 1.0000x reference)
#include <cuda_runtime.h>
#include <math.h>

#define EPSF 1e-6f
#define BLK 96

struct V3 { float x, y, z; };

__device__ __forceinline__ V3 operator+(V3 a, V3 b){ return {a.x+b.x, a.y+b.y, a.z+b.z}; }
__device__ __forceinline__ V3 operator-(V3 a, V3 b){ return {a.x-b.x, a.y-b.y, a.z-b.z}; }
__device__ __forceinline__ V3 operator*(V3 a, float s){ return {a.x*s, a.y*s, a.z*s}; }
__device__ __forceinline__ float dot3(V3 a, V3 b){ return a.x*b.x + a.y*b.y + a.z*b.z; }
__device__ __forceinline__ V3 cross3(V3 a, V3 b){
    return { a.y*b.z - a.z*b.y, a.z*b.x - a.x*b.z, a.x*b.y - a.y*b.x };
}
__device__ __forceinline__ float nrm3(V3 a){ return sqrtf(dot3(a,a)); }
__device__ __forceinline__ V3 unitv(V3 a){ float inv = 1.0f/(nrm3(a)+EPSF); return a*inv; }
__device__ __forceinline__ float clampd(float x){ return fminf(fmaxf(x, -1.0f+EPSF), 1.0f-EPSF); }

struct M3 { float a[9]; };

__device__ __forceinline__ V3 mv(const M3& R, V3 v){
    return { R.a[0]*v.x + R.a[1]*v.y + R.a[2]*v.z,
             R.a[3]*v.x + R.a[4]*v.y + R.a[5]*v.z,
             R.a[6]*v.x + R.a[7]*v.y + R.a[8]*v.z };
}

// smem joint accessors (per-thread stride 63 floats; odd stride -> conflict-free)
__device__ __forceinline__ V3 ld3(const float* sp, int j){
    return { sp[3*j], sp[3*j+1], sp[3*j+2] };
}
__device__ __forceinline__ void st3(float* sp, int j, V3 v){
    sp[3*j] = v.x; sp[3*j+1] = v.y; sp[3*j+2] = v.z;
}

// Rodrigues matrix from UNIT axis
__device__ __forceinline__ M3 rotmat_u(V3 a, float c, float s){
    float C = 1.0f - c;
    M3 R;
    R.a[0] = c + a.x*a.x*C;     R.a[1] = a.x*a.y*C - a.z*s; R.a[2] = a.x*a.z*C + a.y*s;
    R.a[3] = a.y*a.x*C + a.z*s; R.a[4] = c + a.y*a.y*C;     R.a[5] = a.y*a.z*C - a.x*s;
    R.a[6] = a.z*a.x*C - a.y*s; R.a[7] = a.z*a.y*C + a.x*s; R.a[8] = c + a.z*a.z*C;
    return R;
}

// getrot with factored sign decision:
//  d0 = (R(+dif)sv)·ev = t1 + t2 ; d1 = (R(-dif)sv)·ev = t1 - t2
//  |d0|>|d1| <=> t1*t2 > 0. Reference picks R(-dif) on tie.
__device__ __forceinline__ M3 getrot(float angle, float flexRatio, V3 axis, V3 sv, V3 ev){
    const float ANGLEP = 0.34906585039886590f;  // pi/9
    const float TH120  = 2.09439506666666650f;  // 3.1415926/180*120
    angle = (angle > TH120) ? (3.1415926f - angle) : angle;
    float dif = fmaxf(angle - ANGLEP, 0.0f) * flexRatio;
    float s, c;
    sincosf(dif, &s, &c);
    V3 a = unitv(axis);
    float C  = 1.0f - c;
    float t1 = c*dot3(sv, ev) + C*dot3(a, sv)*dot3(a, ev);
    float t2 = s*dot3(cross3(a, sv), ev);
    if (!(t1*t2 > 0.0f)) s = -s;
    return rotmat_u(a, c, s);
}

// Smallest eigenvector of symmetric 3x3 (analytic + two Rayleigh refinements).
__device__ __forceinline__ V3 smallest_evec(float a00, float a01, float a02,
                                            float a11, float a12, float a22){
    float m   = (a00 + a11 + a22) * (1.0f/3.0f);
    float b00 = a00 - m, b11 = a11 - m, b22 = a22 - m;
    float p1  = a01*a01 + a02*a02 + a12*a12;
    float p2  = b00*b00 + b11*b11 + b22*b22 + 2.0f*p1;
    float p   = sqrtf(fmaxf(p2*(1.0f/6.0f), 1e-30f));
    float invp = 1.0f/p;
    float det = b00*(b11*b22 - a12*a12)
              - a01*(a01*b22 - a12*a02)
              + a02*(a01*a12 - b11*a02);
    float r = det * 0.5f * invp*invp*invp;
    r = fminf(fmaxf(r, -1.0f), 1.0f);
    float phi = acosf(r) * (1.0f/3.0f);
    float lam = m + 2.0f*p*cosf(phi + 2.0943951023931953f); // smallest eigenvalue

    V3 v;
    #pragma unroll
    for (int it = 0; it < 3; it++) {
        V3 r0 = { a00 - lam, a01, a02 };
        V3 r1 = { a01, a11 - lam, a12 };
        V3 r2 = { a02, a12, a22 - lam };
        V3 c0 = cross3(r0, r1), c1 = cross3(r0, r2), c2 = cross3(r1, r2);
        float l0 = dot3(c0,c0), l1 = dot3(c1,c1), l2 = dot3(c2,c2);
        V3 best = c0; float lb = l0;
        if (l1 > lb) { best = c1; lb = l1; }
        if (l2 > lb) { best = c2; lb = l2; }
        v = best * rsqrtf(fmaxf(lb, 1e-30f));
        if (it < 2) {
            float Av0 = a00*v.x + a01*v.y + a02*v.z;
            float Av1 = a01*v.x + a11*v.y + a12*v.z;
            float Av2 = a02*v.x + a12*v.y + a22*v.z;
            lam = v.x*Av0 + v.y*Av1 + v.z*Av2;
        }
    }
    return v;
}

// planarize one finger (4 joints in smem, modified in place)
__device__ __forceinline__ void plan4(float* sp, int i0, int i1, int i2, int i3){
    V3 p0 = ld3(sp,i0), p1 = ld3(sp,i1), p2 = ld3(sp,i2), p3 = ld3(sp,i3);
    V3 cm = (p0 + p1 + p2 + p3) * 0.25f;
    V3 d0 = p0 - cm, d1 = p1 - cm, d2 = p2 - cm, d3 = p3 - cm;
    float a00 = d0.x*d0.x + d1.x*d1.x + d2.x*d2.x + d3.x*d3.x;
    float a01 = d0.x*d0.y + d1.x*d1.y + d2.x*d2.y + d3.x*d3.y;
    float a02 = d0.x*d0.z + d1.x*d1.z + d2.x*d2.z + d3.x*d3.z;
    float a11 = d0.y*d0.y + d1.y*d1.y + d2.y*d2.y + d3.y*d3.y;
    float a12 = d0.y*d0.z + d1.y*d1.z + d2.y*d2.z + d3.y*d3.z;
    float a22 = d0.z*d0.z + d1.z*d1.z + d2.z*d2.z + d3.z*d3.z;
    V3 n = smallest_evec(a00, a01, a02, a11, a12, a22);
    float vd = -dot3(n, cm);
    float t;
    t = dot3(p0, n) + vd; st3(sp, i0, p0 - n*t);
    t = dot3(p1, n) + vd; st3(sp, i1, p1 - n*t);
    t = dot3(p2, n) + vd; st3(sp, i2, p2 - n*t);
    t = dot3(p3, n) + vd; st3(sp, i3, p3 - n*t);
}

// abduction for one finger; rectC/rectS are compile-time sincos of RECTIFY[i]
__device__ __forceinline__ void abduct(float* sp, int ia, int ib,
                                       float rectC, float rectS,
                                       int imcp, int ipip, int idip, int itip){
    V3 w  = ld3(sp, 0);
    V3 pa = ld3(sp, ia) - w, pb = ld3(sp, ib) - w;
    V3 mcp = ld3(sp, imcp), pip = ld3(sp, ipip);

    V3 palm = unitv(cross3(pa, pb));
    float vd   = -dot3(mcp, palm);
    float dist = dot3(pip, palm) + vd;
    V3 projpip = pip - palm*dist;

    V3 d  = pip - mcp;
    float dis = nrm3(d);
    V3 mcppip = d * (1.0f/(dis + EPSF));

    V3 e  = projpip - mcp;
    float lene = nrm3(e);
    V3 mcpproj = e * (1.0f/(lene + EPSF));
    float flex = lene / (dis + EPSF);
    flex = (flex < 0.3f) ? 0.0f : flex;

    V3 wristmcp = unitv(mcp - w);
    float cv = clampd(dot3(wristmcp, mcppip));
    bool overflex = cv < 0.00079632671073326f;   // == acos(cv) > 1.57

    // rect = R(palm, RECTIFY) * wristmcp  via vector Rodrigues (palm ~ unit)
    float Cr = 1.0f - rectC;
    V3 axw = cross3(palm, wristmcp);
    float adw = dot3(palm, wristmcp);
    V3 rect = wristmcp*rectC + axw*rectS + palm*(adw*Cr);

    float ang = acosf(clampd(dot3(rect, mcpproj)));
    if (overflex) ang = 0.0f;
    M3 R = getrot(ang, flex, palm, mcpproj, wristmcp);

    st3(sp, ipip, mv(R, pip - mcp) + mcp);
    V3 c;
    c = ld3(sp, idip); st3(sp, idip, mv(R, c - mcp) + mcp);
    c = ld3(sp, itip); st3(sp, itip, mv(R, c - mcp) + mcp);
}

// plane rotation for one finger; rotates DIP & TIP about PIP
__device__ __forceinline__ void planerot(float* sp, int ia, int ib,
                                         int imcp, int ipip, int idip, int itip){
    V3 w  = ld3(sp, 0);
    V3 pa = ld3(sp, ia) - w, pb = ld3(sp, ib) - w;
    V3 mcp = ld3(sp, imcp), pip = ld3(sp, ipip), dip = ld3(sp, idip);

    V3 mcppip = unitv(pip - mcp);
    V3 pipdip = unitv(dip - pip);
    bool maskline = fabsf(dot3(mcppip, pipdip)) > 0.95f;
    V3 cdir = unitv(cross3(mcppip, pipdip));
    V3 palm = unitv(cross3(pa, pb));
    V3 stdv = unitv(cross3(unitv(mcp - w), palm));
    float ang = acosf(clampd(dot3(cdir, stdv)));
    if (maskline) ang = 0.0f;
    M3 R = getrot(ang, 1.0f, mcppip, cdir, stdv);

    st3(sp, idip, mv(R, dip - pip) + pip);
    V3 c = ld3(sp, itip);
    st3(sp, itip, mv(R, c - pip) + pip);
}

__global__ void __launch_bounds__(BLK, 9)
handpose_kernel(const float* __restrict__ in, float* __restrict__ out, int N){
    __shared__ float s[BLK * 63];
    int base = blockIdx.x * BLK;
    int nE = N - base; if (nE > BLK) nE = BLK;
    int nF = nE * 63;
    const float* gin = in + (long long)base * 63;

    if (nE == BLK) {
        const float4* g4 = (const float4*)gin;       // base*63*4 B divisible by 16
        float4* s4 = (float4*)s;
        #pragma unroll
        for (int k = threadIdx.x; k < (BLK*63)/4; k += BLK)
            s4[k] = g4[k];
    } else {
        for (int k = threadIdx.x; k < nF; k += BLK) s[k] = gin[k];
    }
    __syncthreads();

    if ((int)threadIdx.x < nE) {
        float* sp = s + threadIdx.x * 63;

        // ---- planarize #1 ----
        plan4(sp, 1,  2,  3,  17);
        plan4(sp, 4,  5,  6,  18);
        plan4(sp, 10, 11, 12, 19);
        plan4(sp, 7,  8,  9,  20);
        plan4(sp, 13, 14, 15, 16);

        // ---- abduction ----  cos/sin of RECTIFY[i] as literals
        abduct(sp, 1,  4,  0.98219268f,  0.18787768f,  1,  2,  3,  17);  // 0.189
        abduct(sp, 4,  10, 0.99115533f,  0.13270742f,  4,  5,  6,  18);  // 0.1331
        abduct(sp, 10, 7,  0.98890531f, -0.14855814f, 10, 11, 12, 19);   // -0.1491
        abduct(sp, 7,  1,  0.99939799f,  0.03469304f,  7,  8,  9,  20);  // 0.0347
        abduct(sp, 13, 1,  1.0f,         0.0f,        13, 14, 15, 16);   // 0.0

        // ---- plane rotation (fingers 0..3) ----
        planerot(sp, 1,  4,  1,  2,  3,  17);
        planerot(sp, 4,  10, 4,  5,  6,  18);
        planerot(sp, 10, 7,  10, 11, 12, 19);
        planerot(sp, 7,  1,  7,  8,  9,  20);

        // ---- planarize #2 ----
        plan4(sp, 1,  2,  3,  17);
        plan4(sp, 4,  5,  6,  18);
        plan4(sp, 10, 11, 12, 19);
        plan4(sp, 7,  8,  9,  20);
        plan4(sp, 13, 14, 15, 16);
    }
    __syncthreads();

    float* gout = out + (long long)base * 63;
    if (nE == BLK) {
        const float4* s4 = (const float4*)s;
        float4* g4 = (float4*)gout;
        #pragma unroll
        for (int k = threadIdx.x; k < (BLK*63)/4; k += BLK)
            g4[k] = s4[k];
    } else {
        for (int k = threadIdx.x; k < nF; k += BLK) gout[k] = s[k];
    }
}

extern "C" void kernel_launch(void* const* d_in, const int* in_sizes, int n_in,
                              void* d_out, int out_size){
    const float* in = (const float*)d_in[0];
    float* out = (float*)d_out;
    int N = in_sizes[0] / 63;
    int grid = (N + BLK - 1) / BLK;
    handpose_kernel<<<grid, BLK>>>(in, out, N);
}

// round 4
// speedup vs baseline: 1.0458x; 1.0458x over previous
#include <cuda_runtime.h>
#include <math.h>

#define EPSF 1e-6f
#define BLK 128

struct V3 { float x, y, z; };

__device__ __forceinline__ V3 operator+(V3 a, V3 b){ return {a.x+b.x, a.y+b.y, a.z+b.z}; }
__device__ __forceinline__ V3 operator-(V3 a, V3 b){ return {a.x-b.x, a.y-b.y, a.z-b.z}; }
__device__ __forceinline__ V3 operator*(V3 a, float s){ return {a.x*s, a.y*s, a.z*s}; }
__device__ __forceinline__ float dot3(V3 a, V3 b){ return a.x*b.x + a.y*b.y + a.z*b.z; }
__device__ __forceinline__ V3 cross3(V3 a, V3 b){
    return { a.y*b.z - a.z*b.y, a.z*b.x - a.x*b.z, a.x*b.y - a.y*b.x };
}
__device__ __forceinline__ float nrm3(V3 a){ return sqrtf(dot3(a,a)); }
__device__ __forceinline__ V3 unitv(V3 a){
    float inv = __fdividef(1.0f, nrm3(a)+EPSF); return a*inv;
}
__device__ __forceinline__ float clampd(float x){ return fminf(fmaxf(x, -1.0f+EPSF), 1.0f-EPSF); }

struct M3 { float a[9]; };

__device__ __forceinline__ V3 mv(const M3& R, V3 v){
    return { R.a[0]*v.x + R.a[1]*v.y + R.a[2]*v.z,
             R.a[3]*v.x + R.a[4]*v.y + R.a[5]*v.z,
             R.a[6]*v.x + R.a[7]*v.y + R.a[8]*v.z };
}

// smem joint accessors (per-thread stride 63 floats; odd stride -> conflict-free)
__device__ __forceinline__ V3 ld3(const float* sp, int j){
    return { sp[3*j], sp[3*j+1], sp[3*j+2] };
}
__device__ __forceinline__ void st3(float* sp, int j, V3 v){
    sp[3*j] = v.x; sp[3*j+1] = v.y; sp[3*j+2] = v.z;
}

// Rodrigues matrix from UNIT axis
__device__ __forceinline__ M3 rotmat_u(V3 a, float c, float s){
    float C = 1.0f - c;
    M3 R;
    R.a[0] = c + a.x*a.x*C;     R.a[1] = a.x*a.y*C - a.z*s; R.a[2] = a.x*a.z*C + a.y*s;
    R.a[3] = a.y*a.x*C + a.z*s; R.a[4] = c + a.y*a.y*C;     R.a[5] = a.y*a.z*C - a.x*s;
    R.a[6] = a.z*a.x*C - a.y*s; R.a[7] = a.z*a.y*C + a.x*s; R.a[8] = c + a.z*a.z*C;
    return R;
}

// Sign-resolved rotation from (c,s) about unit axis:
//  d0 = (R(+)sv)·ev = t1 + t2 ; d1 = (R(-)sv)·ev = t1 - t2 ; |d0|>|d1| <=> t1*t2>0.
//  Reference picks R(-) on tie.
__device__ __forceinline__ M3 pick_rot(V3 a, float c, float s, V3 sv, V3 ev){
    float C  = 1.0f - c;
    float t1 = c*dot3(sv, ev) + C*dot3(a, sv)*dot3(a, ev);
    float t2 = s*dot3(cross3(a, sv), ev);
    if (!(t1*t2 > 0.0f)) s = -s;
    return rotmat_u(a, c, s);
}

// getrot for abduction (flexRatio scales the angle -> needs real sincos)
__device__ __forceinline__ M3 getrot(float angle, float flexRatio, V3 axis, V3 sv, V3 ev){
    const float ANGLEP = 0.34906585039886590f;  // pi/9
    const float TH120  = 2.09439506666666650f;  // 3.1415926/180*120
    angle = (angle > TH120) ? (3.1415926f - angle) : angle;
    float dif = fmaxf(angle - ANGLEP, 0.0f) * flexRatio;
    float s, c;
    sincosf(dif, &s, &c);
    return pick_rot(unitv(axis), c, s, sv, ev);
}

// Smallest eigenvector of symmetric 3x3 (analytic + two Rayleigh refinements).
__device__ __forceinline__ V3 smallest_evec(float a00, float a01, float a02,
                                            float a11, float a12, float a22){
    float m   = (a00 + a11 + a22) * (1.0f/3.0f);
    float b00 = a00 - m, b11 = a11 - m, b22 = a22 - m;
    float p1  = a01*a01 + a02*a02 + a12*a12;
    float p2  = b00*b00 + b11*b11 + b22*b22 + 2.0f*p1;
    float p   = sqrtf(fmaxf(p2*(1.0f/6.0f), 1e-30f));
    float invp = __fdividef(1.0f, p);
    float det = b00*(b11*b22 - a12*a12)
              - a01*(a01*b22 - a12*a02)
              + a02*(a01*a12 - b11*a02);
    float r = det * 0.5f * invp*invp*invp;
    r = fminf(fmaxf(r, -1.0f), 1.0f);
    float phi = acosf(r) * (1.0f/3.0f);
    float lam = m + 2.0f*p*cosf(phi + 2.0943951023931953f); // smallest eigenvalue

    V3 v;
    #pragma unroll
    for (int it = 0; it < 3; it++) {
        V3 r0 = { a00 - lam, a01, a02 };
        V3 r1 = { a01, a11 - lam, a12 };
        V3 r2 = { a02, a12, a22 - lam };
        V3 c0 = cross3(r0, r1), c1 = cross3(r0, r2), c2 = cross3(r1, r2);
        float l0 = dot3(c0,c0), l1 = dot3(c1,c1), l2 = dot3(c2,c2);
        V3 best = c0; float lb = l0;
        if (l1 > lb) { best = c1; lb = l1; }
        if (l2 > lb) { best = c2; lb = l2; }
        v = best * rsqrtf(fmaxf(lb, 1e-30f));
        if (it < 2) {
            float Av0 = a00*v.x + a01*v.y + a02*v.z;
            float Av1 = a01*v.x + a11*v.y + a12*v.z;
            float Av2 = a02*v.x + a12*v.y + a22*v.z;
            lam = v.x*Av0 + v.y*Av1 + v.z*Av2;
        }
    }
    return v;
}

// planarize one finger (4 joints in smem, modified in place)
__device__ __forceinline__ void plan4(float* sp, int i0, int i1, int i2, int i3){
    V3 p0 = ld3(sp,i0), p1 = ld3(sp,i1), p2 = ld3(sp,i2), p3 = ld3(sp,i3);
    V3 cm = (p0 + p1 + p2 + p3) * 0.25f;
    V3 d0 = p0 - cm, d1 = p1 - cm, d2 = p2 - cm, d3 = p3 - cm;
    float a00 = d0.x*d0.x + d1.x*d1.x + d2.x*d2.x + d3.x*d3.x;
    float a01 = d0.x*d0.y + d1.x*d1.y + d2.x*d2.y + d3.x*d3.y;
    float a02 = d0.x*d0.z + d1.x*d1.z + d2.x*d2.z + d3.x*d3.z;
    float a11 = d0.y*d0.y + d1.y*d1.y + d2.y*d2.y + d3.y*d3.y;
    float a12 = d0.y*d0.z + d1.y*d1.z + d2.y*d2.z + d3.y*d3.z;
    float a22 = d0.z*d0.z + d1.z*d1.z + d2.z*d2.z + d3.z*d3.z;
    V3 n = smallest_evec(a00, a01, a02, a11, a12, a22);
    float vd = -dot3(n, cm);
    float t;
    t = dot3(p0, n) + vd; st3(sp, i0, p0 - n*t);
    t = dot3(p1, n) + vd; st3(sp, i1, p1 - n*t);
    t = dot3(p2, n) + vd; st3(sp, i2, p2 - n*t);
    t = dot3(p3, n) + vd; st3(sp, i3, p3 - n*t);
}

// abduction for one finger; rectC/rectS are compile-time sincos of RECTIFY[i]
__device__ __forceinline__ void abduct(float* sp, int ia, int ib,
                                       float rectC, float rectS,
                                       int imcp, int ipip, int idip, int itip){
    V3 w  = ld3(sp, 0);
    V3 pa = ld3(sp, ia) - w, pb = ld3(sp, ib) - w;
    V3 mcp = ld3(sp, imcp), pip = ld3(sp, ipip);

    V3 palm = unitv(cross3(pa, pb));
    float vd   = -dot3(mcp, palm);
    float dist = dot3(pip, palm) + vd;
    V3 projpip = pip - palm*dist;

    V3 d  = pip - mcp;
    float dis = nrm3(d);
    float invdis = __fdividef(1.0f, dis + EPSF);
    V3 mcppip = d * invdis;

    V3 e  = projpip - mcp;
    float lene = nrm3(e);
    V3 mcpproj = e * __fdividef(1.0f, lene + EPSF);
    float flex = lene * invdis;
    flex = (flex < 0.3f) ? 0.0f : flex;

    V3 wristmcp = unitv(mcp - w);
    float cv = clampd(dot3(wristmcp, mcppip));
    bool overflex = cv < 0.00079632671073326f;   // == acos(cv) > 1.57

    // rect = R(palm, RECTIFY) * wristmcp  via vector Rodrigues (palm ~ unit)
    float Cr = 1.0f - rectC;
    V3 axw = cross3(palm, wristmcp);
    float adw = dot3(palm, wristmcp);
    V3 rect = wristmcp*rectC + axw*rectS + palm*(adw*Cr);

    float ang = acosf(clampd(dot3(rect, mcpproj)));
    if (overflex) ang = 0.0f;
    M3 R = getrot(ang, flex, palm, mcpproj, wristmcp);

    st3(sp, ipip, mv(R, pip - mcp) + mcp);
    V3 c;
    c = ld3(sp, idip); st3(sp, idip, mv(R, c - mcp) + mcp);
    c = ld3(sp, itip); st3(sp, itip, mv(R, c - mcp) + mcp);
}

// plane rotation for one finger; rotates DIP & TIP about PIP.
// flexRatio==1 here, so cos/sin(dif) are computed analytically from the dot
// product (no acos/sincos): a = acos(x) [flipped if a>120deg], dif = max(a-AP,0),
// cos(dif)=ca*cAP+sa*sAP, sin(dif)=sa*cAP-ca*sAP.
__device__ __forceinline__ void planerot(float* sp, int ia, int ib,
                                         int imcp, int ipip, int idip, int itip){
    const float COS_TH120 = -0.49999997f;     // cos(3.1415926/180*120)
    const float cAP = 0.93969262078590838f;   // cos(pi/9)
    const float sAP = 0.34202014332566871f;   // sin(pi/9)

    V3 w  = ld3(sp, 0);
    V3 pa = ld3(sp, ia) - w, pb = ld3(sp, ib) - w;
    V3 mcp = ld3(sp, imcp), pip = ld3(sp, ipip), dip = ld3(sp, idip);

    V3 mcppip = unitv(pip - mcp);
    V3 pipdip = unitv(dip - pip);
    bool maskline = fabsf(dot3(mcppip, pipdip)) > 0.95f;
    V3 cdir = unitv(cross3(mcppip, pipdip));
    V3 palm = unitv(cross3(pa, pb));
    V3 stdv = unitv(cross3(unitv(mcp - w), palm));

    float x = clampd(dot3(cdir, stdv));
    float ca = (x < COS_TH120) ? -x : x;      // cos(effective angle)
    float sa = sqrtf(fmaxf(1.0f - x*x, 0.0f)); // sin(effective angle) >= 0
    if (maskline) { ca = 1.0f; sa = 0.0f; }    // ang = 0

    float c, s;
    if (ca >= cAP) { c = 1.0f; s = 0.0f; }     // a <= pi/9 -> dif = 0
    else {
        c = ca*cAP + sa*sAP;                   // cos(a - AP)
        s = sa*cAP - ca*sAP;                   // sin(a - AP)
    }
    M3 R = pick_rot(mcppip, c, s, cdir, stdv); // mcppip already unit

    st3(sp, idip, mv(R, dip - pip) + pip);
    V3 cc = ld3(sp, itip);
    st3(sp, itip, mv(R, cc - pip) + pip);
}

__global__ void __launch_bounds__(BLK, 6)
handpose_kernel(const float* __restrict__ in, float* __restrict__ out, int N){
    __shared__ float s[BLK * 63];
    int base = blockIdx.x * BLK;
    int nE = N - base; if (nE > BLK) nE = BLK;
    int nF = nE * 63;
    const float* gin = in + (long long)base * 63;

    if (nE == BLK) {
        const float4* g4 = (const float4*)gin;   // base*63*4 bytes divisible by 16
        float4* s4 = (float4*)s;
        for (int k = threadIdx.x; k < (BLK*63)/4; k += BLK)
            s4[k] = g4[k];
    } else {
        for (int k = threadIdx.x; k < nF; k += BLK) s[k] = gin[k];
    }
    __syncthreads();

    if ((int)threadIdx.x < nE) {
        float* sp = s + threadIdx.x * 63;

        // ---- planarize #1 ----
        plan4(sp, 1,  2,  3,  17);
        plan4(sp, 4,  5,  6,  18);
        plan4(sp, 10, 11, 12, 19);
        plan4(sp, 7,  8,  9,  20);
        plan4(sp, 13, 14, 15, 16);

        // ---- abduction ---- cos/sin of RECTIFY[i] as literals
        abduct(sp, 1,  4,  0.98219268f,  0.18787768f,  1,  2,  3,  17);  // 0.189
        abduct(sp, 4,  10, 0.99115533f,  0.13270742f,  4,  5,  6,  18);  // 0.1331
        abduct(sp, 10, 7,  0.98890531f, -0.14855814f, 10, 11, 12, 19);   // -0.1491
        abduct(sp, 7,  1,  0.99939799f,  0.03469304f,  7,  8,  9,  20);  // 0.0347
        abduct(sp, 13, 1,  1.0f,         0.0f,        13, 14, 15, 16);   // 0.0

        // ---- plane rotation (fingers 0..3) ----
        planerot(sp, 1,  4,  1,  2,  3,  17);
        planerot(sp, 4,  10, 4,  5,  6,  18);
        planerot(sp, 10, 7,  10, 11, 12, 19);
        planerot(sp, 7,  1,  7,  8,  9,  20);

        // ---- planarize #2 ----
        plan4(sp, 1,  2,  3,  17);
        plan4(sp, 4,  5,  6,  18);
        plan4(sp, 10, 11, 12, 19);
        plan4(sp, 7,  8,  9,  20);
        plan4(sp, 13, 14, 15, 16);
    }
    __syncthreads();

    float* gout = out + (long long)base * 63;
    if (nE == BLK) {
        const float4* s4 = (const float4*)s;
        float4* g4 = (float4*)gout;
        for (int k = threadIdx.x; k < (BLK*63)/4; k += BLK)
            g4[k] = s4[k];
    } else {
        for (int k = threadIdx.x; k < nF; k += BLK) gout[k] = s[k];
    }
}

extern "C" void kernel_launch(void* const* d_in, const int* in_sizes, int n_in,
                              void* d_out, int out_size){
    const float* in = (const float*)d_in[0];
    float* out = (float*)d_out;
    int N = in_sizes[0] / 63;
    int grid = (N + BLK - 1) / BLK;
    handpose_kernel<<<grid, BLK>>>(in, out, N);
}

// round 5
// speedup vs baseline: 1.4590x; 1.3951x over previous
#include <cuda_runtime.h>
#include <math.h>

#define EPSF 1e-6f
#define HANDS 32
#define BLKT 160   // 32 hands x 5 finger-warps

struct V3 { float x, y, z; };

__device__ __forceinline__ V3 operator+(V3 a, V3 b){ return {a.x+b.x, a.y+b.y, a.z+b.z}; }
__device__ __forceinline__ V3 operator-(V3 a, V3 b){ return {a.x-b.x, a.y-b.y, a.z-b.z}; }
__device__ __forceinline__ V3 operator*(V3 a, float s){ return {a.x*s, a.y*s, a.z*s}; }
__device__ __forceinline__ float dot3(V3 a, V3 b){ return a.x*b.x + a.y*b.y + a.z*b.z; }
__device__ __forceinline__ V3 cross3(V3 a, V3 b){
    return { a.y*b.z - a.z*b.y, a.z*b.x - a.x*b.z, a.x*b.y - a.y*b.x };
}
__device__ __forceinline__ float nrm3(V3 a){ return sqrtf(dot3(a,a)); }
__device__ __forceinline__ V3 unitv(V3 a){
    float inv = __fdividef(1.0f, nrm3(a)+EPSF); return a*inv;
}
__device__ __forceinline__ float clampd(float x){ return fminf(fmaxf(x, -1.0f+EPSF), 1.0f-EPSF); }

struct M3 { float a[9]; };

__device__ __forceinline__ V3 mv(const M3& R, V3 v){
    return { R.a[0]*v.x + R.a[1]*v.y + R.a[2]*v.z,
             R.a[3]*v.x + R.a[4]*v.y + R.a[5]*v.z,
             R.a[6]*v.x + R.a[7]*v.y + R.a[8]*v.z };
}

// smem joint accessors (per-hand stride 63 floats; odd stride -> conflict-free)
__device__ __forceinline__ V3 ld3(const float* sp, int j){
    return { sp[3*j], sp[3*j+1], sp[3*j+2] };
}
__device__ __forceinline__ void st3(float* sp, int j, V3 v){
    sp[3*j] = v.x; sp[3*j+1] = v.y; sp[3*j+2] = v.z;
}

// per-finger tables
__constant__ int   cMCP[5] = {1, 4, 10, 7, 13};
__constant__ int   cPIP[5] = {2, 5, 11, 8, 14};
__constant__ int   cDIP[5] = {3, 6, 12, 9, 15};
__constant__ int   cTIP[5] = {17, 18, 19, 20, 16};
__constant__ int   cPB [5] = {4, 10, 7, 1, 1};           // palm b index (a index == MCP)
__constant__ float cRC [5] = {0.98219268f, 0.99115533f, 0.98890531f, 0.99939799f, 1.0f};
__constant__ float cRS [5] = {0.18787768f, 0.13270742f, -0.14855814f, 0.03469304f, 0.0f};

// Rodrigues matrix from UNIT axis
__device__ __forceinline__ M3 rotmat_u(V3 a, float c, float s){
    float C = 1.0f - c;
    M3 R;
    R.a[0] = c + a.x*a.x*C;     R.a[1] = a.x*a.y*C - a.z*s; R.a[2] = a.x*a.z*C + a.y*s;
    R.a[3] = a.y*a.x*C + a.z*s; R.a[4] = c + a.y*a.y*C;     R.a[5] = a.y*a.z*C - a.x*s;
    R.a[6] = a.z*a.x*C - a.y*s; R.a[7] = a.z*a.y*C + a.x*s; R.a[8] = c + a.z*a.z*C;
    return R;
}

// Sign-resolved rotation: d0=(R(+)sv)·ev = t1+t2 ; d1=(R(-)sv)·ev = t1-t2.
// |d0|>|d1| <=> t1*t2>0 ; reference picks R(-) on tie.
__device__ __forceinline__ M3 pick_rot(V3 a, float c, float s, V3 sv, V3 ev){
    float C  = 1.0f - c;
    float t1 = c*dot3(sv, ev) + C*dot3(a, sv)*dot3(a, ev);
    float t2 = s*dot3(cross3(a, sv), ev);
    if (!(t1*t2 > 0.0f)) s = -s;
    return rotmat_u(a, c, s);
}

// getrot for abduction (angle scaled by flexRatio -> real sincos)
__device__ __forceinline__ M3 getrot(float angle, float flexRatio, V3 axis, V3 sv, V3 ev){
    const float ANGLEP = 0.34906585039886590f;  // pi/9
    const float TH120  = 2.09439506666666650f;  // 3.1415926/180*120
    angle = (angle > TH120) ? (3.1415926f - angle) : angle;
    float dif = fmaxf(angle - ANGLEP, 0.0f) * flexRatio;
    float s, c;
    sincosf(dif, &s, &c);
    return pick_rot(unitv(axis), c, s, sv, ev);
}

// Smallest eigenvector of symmetric 3x3 (analytic + two Rayleigh refinements).
__device__ __forceinline__ V3 smallest_evec(float a00, float a01, float a02,
                                            float a11, float a12, float a22){
    float m   = (a00 + a11 + a22) * (1.0f/3.0f);
    float b00 = a00 - m, b11 = a11 - m, b22 = a22 - m;
    float p1  = a01*a01 + a02*a02 + a12*a12;
    float p2  = b00*b00 + b11*b11 + b22*b22 + 2.0f*p1;
    float p   = sqrtf(fmaxf(p2*(1.0f/6.0f), 1e-30f));
    float invp = __fdividef(1.0f, p);
    float det = b00*(b11*b22 - a12*a12)
              - a01*(a01*b22 - a12*a02)
              + a02*(a01*a12 - b11*a02);
    float r = det * 0.5f * invp*invp*invp;
    r = fminf(fmaxf(r, -1.0f), 1.0f);
    float phi = acosf(r) * (1.0f/3.0f);
    float lam = m + 2.0f*p*cosf(phi + 2.0943951023931953f); // smallest eigenvalue

    V3 v;
    #pragma unroll
    for (int it = 0; it < 3; it++) {
        V3 r0 = { a00 - lam, a01, a02 };
        V3 r1 = { a01, a11 - lam, a12 };
        V3 r2 = { a02, a12, a22 - lam };
        V3 c0 = cross3(r0, r1), c1 = cross3(r0, r2), c2 = cross3(r1, r2);
        float l0 = dot3(c0,c0), l1 = dot3(c1,c1), l2 = dot3(c2,c2);
        V3 best = c0; float lb = l0;
        if (l1 > lb) { best = c1; lb = l1; }
        if (l2 > lb) { best = c2; lb = l2; }
        v = best * rsqrtf(fmaxf(lb, 1e-30f));
        if (it < 2) {
            float Av0 = a00*v.x + a01*v.y + a02*v.z;
            float Av1 = a01*v.x + a11*v.y + a12*v.z;
            float Av2 = a02*v.x + a12*v.y + a22*v.z;
            lam = v.x*Av0 + v.y*Av1 + v.z*Av2;
        }
    }
    return v;
}

// planarize one finger (4 joints in smem, modified in place)
__device__ __forceinline__ void plan4(float* sp, int i0, int i1, int i2, int i3){
    V3 p0 = ld3(sp,i0), p1 = ld3(sp,i1), p2 = ld3(sp,i2), p3 = ld3(sp,i3);
    V3 cm = (p0 + p1 + p2 + p3) * 0.25f;
    V3 d0 = p0 - cm, d1 = p1 - cm, d2 = p2 - cm, d3 = p3 - cm;
    float a00 = d0.x*d0.x + d1.x*d1.x + d2.x*d2.x + d3.x*d3.x;
    float a01 = d0.x*d0.y + d1.x*d1.y + d2.x*d2.y + d3.x*d3.y;
    float a02 = d0.x*d0.z + d1.x*d1.z + d2.x*d2.z + d3.x*d3.z;
    float a11 = d0.y*d0.y + d1.y*d1.y + d2.y*d2.y + d3.y*d3.y;
    float a12 = d0.y*d0.z + d1.y*d1.z + d2.y*d2.z + d3.y*d3.z;
    float a22 = d0.z*d0.z + d1.z*d1.z + d2.z*d2.z + d3.z*d3.z;
    V3 n = smallest_evec(a00, a01, a02, a11, a12, a22);
    float vd = -dot3(n, cm);
    float t;
    t = dot3(p0, n) + vd; st3(sp, i0, p0 - n*t);
    t = dot3(p1, n) + vd; st3(sp, i1, p1 - n*t);
    t = dot3(p2, n) + vd; st3(sp, i2, p2 - n*t);
    t = dot3(p3, n) + vd; st3(sp, i3, p3 - n*t);
}

// abduction for one finger
__device__ __forceinline__ void abduct(float* sp, int ib, float rectC, float rectS,
                                       int imcp, int ipip, int idip, int itip){
    V3 w  = ld3(sp, 0);
    V3 mcp = ld3(sp, imcp), pip = ld3(sp, ipip);
    V3 pa = mcp - w, pb = ld3(sp, ib) - w;

    V3 palm = unitv(cross3(pa, pb));
    float vd   = -dot3(mcp, palm);
    float dist = dot3(pip, palm) + vd;
    V3 projpip = pip - palm*dist;

    V3 d  = pip - mcp;
    float dis = nrm3(d);
    float invdis = __fdividef(1.0f, dis + EPSF);
    V3 mcppip = d * invdis;

    V3 e  = projpip - mcp;
    float lene = nrm3(e);
    V3 mcpproj = e * __fdividef(1.0f, lene + EPSF);
    float flex = lene * invdis;
    flex = (flex < 0.3f) ? 0.0f : flex;

    V3 wristmcp = unitv(mcp - w);
    float cv = clampd(dot3(wristmcp, mcppip));
    bool overflex = cv < 0.00079632671073326f;   // == acos(cv) > 1.57

    // rect = R(palm, RECTIFY) * wristmcp  via vector Rodrigues (palm ~ unit)
    float Cr = 1.0f - rectC;
    V3 axw = cross3(palm, wristmcp);
    float adw = dot3(palm, wristmcp);
    V3 rect = wristmcp*rectC + axw*rectS + palm*(adw*Cr);

    float ang = acosf(clampd(dot3(rect, mcpproj)));
    if (overflex) ang = 0.0f;
    M3 R = getrot(ang, flex, palm, mcpproj, wristmcp);

    st3(sp, ipip, mv(R, pip - mcp) + mcp);
    V3 c;
    c = ld3(sp, idip); st3(sp, idip, mv(R, c - mcp) + mcp);
    c = ld3(sp, itip); st3(sp, itip, mv(R, c - mcp) + mcp);
}

// plane rotation (flexRatio==1 -> analytic cos/sin of (a - pi/9), no acos/sincos)
__device__ __forceinline__ void planerot(float* sp, int ib,
                                         int imcp, int ipip, int idip, int itip){
    const float COS_TH120 = -0.49999997f;      // cos(3.1415926/180*120)
    const float cAP = 0.93969262078590838f;    // cos(pi/9)
    const float sAP = 0.34202014332566871f;    // sin(pi/9)

    V3 w  = ld3(sp, 0);
    V3 mcp = ld3(sp, imcp), pip = ld3(sp, ipip), dip = ld3(sp, idip);
    V3 pa = mcp - w, pb = ld3(sp, ib) - w;

    V3 mcppip = unitv(pip - mcp);
    V3 pipdip = unitv(dip - pip);
    bool maskline = fabsf(dot3(mcppip, pipdip)) > 0.95f;
    V3 cdir = unitv(cross3(mcppip, pipdip));
    V3 palm = unitv(cross3(pa, pb));
    V3 stdv = unitv(cross3(unitv(mcp - w), palm));

    float x = clampd(dot3(cdir, stdv));
    float ca = (x < COS_TH120) ? -x : x;
    float sa = sqrtf(fmaxf(1.0f - x*x, 0.0f));
    if (maskline) { ca = 1.0f; sa = 0.0f; }

    float c, s;
    if (ca >= cAP) { c = 1.0f; s = 0.0f; }
    else { c = ca*cAP + sa*sAP; s = sa*cAP - ca*sAP; }
    M3 R = pick_rot(mcppip, c, s, cdir, stdv);

    st3(sp, idip, mv(R, dip - pip) + pip);
    V3 cc = ld3(sp, itip);
    st3(sp, itip, mv(R, cc - pip) + pip);
}

__global__ void __launch_bounds__(BLKT, 6)
handpose_kernel(const float* __restrict__ in, float* __restrict__ out, int N){
    __shared__ float s[HANDS * 63];
    int base = blockIdx.x * HANDS;
    int nE = N - base; if (nE > HANDS) nE = HANDS;
    int nF = nE * 63;
    const float* gin = in + (long long)base * 63;

    if (nE == HANDS) {
        const float4* g4 = (const float4*)gin;   // base*63*4 B divisible by 16
        float4* s4 = (float4*)s;
        for (int k = threadIdx.x; k < (HANDS*63)/4; k += BLKT)
            s4[k] = g4[k];
    } else {
        for (int k = threadIdx.x; k < nF; k += BLKT) s[k] = gin[k];
    }
    __syncthreads();

    int lane = threadIdx.x & 31;   // hand within block
    int f    = threadIdx.x >> 5;   // finger (warp id), 0..4
    bool act = lane < nE;

    int imcp = cMCP[f], ipip = cPIP[f], idip = cDIP[f], itip = cTIP[f];
    int ib   = cPB[f];
    float* sp = s + lane * 63;

    // ---- planarize #1 (all fingers parallel) ----
    if (act) plan4(sp, imcp, ipip, idip, itip);
    __syncthreads();   // abduction reads neighbor MCPs written above

    if (act) {
        // ---- abduction ---- (reads wrist/MCPs [unchanged] + own-finger joints)
        abduct(sp, ib, cRC[f], cRS[f], imcp, ipip, idip, itip);
        // ---- plane rotation (fingers 0..3; reads only own-thread or unchanged) ----
        if (f < 4) planerot(sp, ib, imcp, ipip, idip, itip);
        // ---- planarize #2 (own finger only) ----
        plan4(sp, imcp, ipip, idip, itip);
    }
    __syncthreads();

    float* gout = out + (long long)base * 63;
    if (nE == HANDS) {
        const float4* s4 = (const float4*)s;
        float4* g4 = (float4*)gout;
        for (int k = threadIdx.x; k < (HANDS*63)/4; k += BLKT)
            g4[k] = s4[k];
    } else {
        for (int k = threadIdx.x; k < nF; k += BLKT) gout[k] = s[k];
    }
}

extern "C" void kernel_launch(void* const* d_in, const int* in_sizes, int n_in,
                              void* d_out, int out_size){
    const float* in = (const float*)d_in[0];
    float* out = (float*)d_out;
    int N = in_sizes[0] / 63;
    int grid = (N + HANDS - 1) / HANDS;
    handpose_kernel<<<grid, BLKT>>>(in, out, N);
}